// round 5
// baseline (speedup 1.0000x reference)
#include <cuda_runtime.h>
#include <math.h>

typedef unsigned long long ull;

#define N_NODES 10000
#define N_EDGES 160000
#define HDIM    128
#define NLAYERS 3
#define BN_EPS  1e-5f

#define EDGE_TILES (N_EDGES / 128)        // 1250
#define NODE_TILES ((N_NODES + 63) / 64)  // 157

// ---------------- device scratch ----------------
__device__ float g_coords[N_NODES * 3];
__device__ float g_V[N_NODES * HDIM];
__device__ float g_Vraw[N_NODES * HDIM];   // Pd during edge phase
__device__ float g_VH[N_NODES * HDIM];     // Ps during edge phase
__device__ float g_mi[N_NODES * HDIM];
__device__ float g_accum[N_NODES * 3];
__device__ float g_mij[N_EDGES * HDIM];
__device__ float g_partE[2 * EDGE_TILES * HDIM];
__device__ float g_partN[2 * 160 * HDIM];
__device__ float g_muinv[2 * HDIM];

__device__ __forceinline__ float silu_f(float x) { return x / (1.0f + expf(-x)); }
__device__ __forceinline__ float elu_f(float x)  { return x > 0.0f ? x : (expf(x) - 1.0f); }

__device__ __forceinline__ ull fma2(ull a, ull b, ull c) {
    ull d;
    asm("fma.rn.f32x2 %0, %1, %2, %3;" : "=l"(d) : "l"(a), "l"(b), "l"(c));
    return d;
}
__device__ __forceinline__ float2 unpk(ull v) {
    unsigned lo, hi;
    asm("mov.b64 {%0,%1}, %2;" : "=r"(lo), "=r"(hi) : "l"(v));
    return make_float2(__uint_as_float(lo), __uint_as_float(hi));
}
__device__ __forceinline__ ull dup2(float a) {
    ull d;
    asm("mov.b64 %0, {%1,%1};" : "=l"(d) : "f"(a));
    return d;
}
__device__ __forceinline__ void red_add_v4(float* addr, float4 v) {
    asm volatile("red.global.add.v4.f32 [%0], {%1,%2,%3,%4};"
                 :: "l"(addr), "f"(v.x), "f"(v.y), "f"(v.z), "f"(v.w)
                 : "memory");
}

// tile addressing: row stride 132 floats + 16B row-group swizzle
__device__ __forceinline__ int ts_off(int r, int c) {
    return r * 132 + ((r >> 3) & 1) * 4 + c;
}

// 8-row micro-GEMM over one 16-k slab (2-kk steps, LDS.64 A loads)
__device__ __forceinline__ void gemm_tile(ull (&acc)[8][4], const float* Ts,
                                          const float* Bs, int kbase,
                                          int row0, int col0)
{
    const float* arow = Ts + row0 * 132 + ((row0 >> 3) & 1) * 4 + kbase;
#pragma unroll
    for (int kk = 0; kk < 16; kk += 2) {
        const float* bp0 = Bs + kk * 132 + col0;
        const float* bp1 = bp0 + 132;
        ulonglong2 b01a = *(const ulonglong2*)bp0;
        ulonglong2 b23a = *(const ulonglong2*)(bp0 + 4);
        ulonglong2 b01b = *(const ulonglong2*)bp1;
        ulonglong2 b23b = *(const ulonglong2*)(bp1 + 4);
#pragma unroll
        for (int i = 0; i < 8; i++) {
            float2 a2 = *(const float2*)&arow[i * 132 + kk];
            ull av0 = dup2(a2.x), av1 = dup2(a2.y);
            acc[i][0] = fma2(av0, b01a.x, acc[i][0]);
            acc[i][1] = fma2(av0, b01a.y, acc[i][1]);
            acc[i][2] = fma2(av0, b23a.x, acc[i][2]);
            acc[i][3] = fma2(av0, b23a.y, acc[i][3]);
            acc[i][0] = fma2(av1, b01b.x, acc[i][0]);
            acc[i][1] = fma2(av1, b01b.y, acc[i][1]);
            acc[i][2] = fma2(av1, b23b.x, acc[i][2]);
            acc[i][3] = fma2(av1, b23b.y, acc[i][3]);
        }
    }
}

// 4-row variant (node kernel phase B)
__device__ __forceinline__ void gemm_tile4(ull (&acc)[4][4], const float* Ts,
                                           const float* Bs, int kbase,
                                           int row0, int col0)
{
    const float* arow = Ts + row0 * 132 + ((row0 >> 3) & 1) * 4 + kbase;
#pragma unroll
    for (int kk = 0; kk < 16; kk += 2) {
        const float* bp0 = Bs + kk * 132 + col0;
        const float* bp1 = bp0 + 132;
        ulonglong2 b01a = *(const ulonglong2*)bp0;
        ulonglong2 b23a = *(const ulonglong2*)(bp0 + 4);
        ulonglong2 b01b = *(const ulonglong2*)bp1;
        ulonglong2 b23b = *(const ulonglong2*)(bp1 + 4);
#pragma unroll
        for (int i = 0; i < 4; i++) {
            float2 a2 = *(const float2*)&arow[i * 132 + kk];
            ull av0 = dup2(a2.x), av1 = dup2(a2.y);
            acc[i][0] = fma2(av0, b01a.x, acc[i][0]);
            acc[i][1] = fma2(av0, b01a.y, acc[i][1]);
            acc[i][2] = fma2(av0, b23a.x, acc[i][2]);
            acc[i][3] = fma2(av0, b23a.y, acc[i][3]);
            acc[i][0] = fma2(av1, b01b.x, acc[i][0]);
            acc[i][1] = fma2(av1, b01b.y, acc[i][1]);
            acc[i][2] = fma2(av1, b23b.x, acc[i][2]);
            acc[i][3] = fma2(av1, b23b.y, acc[i][3]);
        }
    }
}

// ---------------- fused edge pipeline ----------------
__global__ __launch_bounds__(256, 2)
void edge_fused_k(const int* __restrict__ srcv, const int* __restrict__ dstv,
                  const float* __restrict__ ee,
                  const float* __restrict__ Ps, const float* __restrict__ Pd,
                  const float* __restrict__ We1_tail,
                  const float* __restrict__ be1,
                  const float* __restrict__ We2, const float* __restrict__ be2,
                  const float* __restrict__ Wx1, const float* __restrict__ bx1,
                  const float* __restrict__ Wx2, const float* __restrict__ bx2,
                  int write_mij)
{
    extern __shared__ float smf[];
    float* Ts    = smf;                   // 16896
    float* Bs    = smf + 16896;           // 4224
    float* wex   = smf + 21120;           // 384
    float* be1s  = smf + 21504;           // 128
    float* wx2s  = smf + 21632;           // 384
    float* bx2s  = smf + 22016;           // 4
    float* diffs = smf + 22020;           // 384
    float* dists = smf + 22404;           // 128
    float* ee0s  = smf + 22532;           // 128
    float* ee1s  = smf + 22660;           // 128
    int*   dsts  = (int*)(smf + 22788);   // 128
    float* es    = smf + 22916;           // 256

    const int tid  = threadIdx.x;
    const int m0   = blockIdx.x * 128;
    const int brow = tid >> 4;
    const int bcol = (tid & 15) * 8;
    const int row0 = (tid >> 4) * 8;
    const int col0 = (tid & 15) * 8;

    if (tid < 128) {
        int mm = m0 + tid;
        int s = srcv[mm], d = dstv[mm];
        float dx = g_coords[d * 3 + 0] - g_coords[s * 3 + 0];
        float dy = g_coords[d * 3 + 1] - g_coords[s * 3 + 1];
        float dz = g_coords[d * 3 + 2] - g_coords[s * 3 + 2];
        diffs[tid * 3 + 0] = dx;
        diffs[tid * 3 + 1] = dy;
        diffs[tid * 3 + 2] = dz;
        dists[tid] = sqrtf(dx * dx + dy * dy + dz * dz);
        dsts[tid] = d;
        ee0s[tid] = ee[mm * 2 + 0];
        ee1s[tid] = ee[mm * 2 + 1];
    }
    es[tid] = 0.f;
    for (int i = tid; i < 384; i += 256) { wex[i] = We1_tail[i]; wx2s[i] = Wx2[i]; }
    if (tid < 128) be1s[tid] = be1[tid];
    if (tid < 3)   bx2s[tid] = bx2[tid];
    __syncthreads();

    // T1 = silu(Ps[src] + Pd[dst] + dist*w + ee@W + be1)
    {
        const int r  = tid >> 1;
        const int mm = m0 + r;
        const int s  = srcv[mm];
        const int d  = dstv[mm];
        const float di = dists[r], e0 = ee0s[r], e1 = ee1s[r];
        const int cb = (tid & 1) * 64;
        const float* psp = Ps + (size_t)s * 128;
        const float* pdp = Pd + (size_t)d * 128;
#pragma unroll 4
        for (int c = cb; c < cb + 64; c += 4) {
            float4 a = *(const float4*)(psp + c);
            float4 b = *(const float4*)(pdp + c);
            float4 o;
            o.x = silu_f(a.x + b.x + di * wex[c+0] + e0 * wex[128+c+0] + e1 * wex[256+c+0] + be1s[c+0]);
            o.y = silu_f(a.y + b.y + di * wex[c+1] + e0 * wex[128+c+1] + e1 * wex[256+c+1] + be1s[c+1]);
            o.z = silu_f(a.z + b.z + di * wex[c+2] + e0 * wex[128+c+2] + e1 * wex[256+c+2] + be1s[c+2]);
            o.w = silu_f(a.w + b.w + di * wex[c+3] + e0 * wex[128+c+3] + e1 * wex[256+c+3] + be1s[c+3]);
            *(float4*)(Ts + ts_off(r, c)) = o;
        }
    }
    __syncthreads();

    auto loadB8 = [&](const float* W, int gk, float* v) {
        float4 x0 = *(const float4*)(W + (size_t)gk * 128 + bcol);
        float4 x1 = *(const float4*)(W + (size_t)gk * 128 + bcol + 4);
        v[0] = x0.x; v[1] = x0.y; v[2] = x0.z; v[3] = x0.w;
        v[4] = x1.x; v[5] = x1.y; v[6] = x1.z; v[7] = x1.w;
    };
    auto storeB = [&](int buf, const float* v) {
        float* base = Bs + buf * 2112 + brow * 132 + bcol;
        *(float4*)(base)     = make_float4(v[0], v[1], v[2], v[3]);
        *(float4*)(base + 4) = make_float4(v[4], v[5], v[6], v[7]);
    };

    ull acc[8][4];

    // mij = silu(T1 @ We2 + be2)
#pragma unroll
    for (int i = 0; i < 8; i++)
#pragma unroll
        for (int j = 0; j < 4; j++) acc[i][j] = 0ULL;
    {
        float vb[8];
        loadB8(We2, brow, vb); storeB(0, vb);
    }
    __syncthreads();
    int buf = 0;
    for (int kt = 0; kt < 8; kt++) {
        float nb[8];
        const bool pre = (kt < 7);
        if (pre) loadB8(We2, (kt + 1) * 16 + brow, nb);
        gemm_tile(acc, Ts, Bs + buf * 2112, kt * 16, row0, col0);
        if (pre) storeB(buf ^ 1, nb);
        __syncthreads();
        buf ^= 1;
    }
    {
        float b[8];
        *(float4*)b       = *(const float4*)(be2 + col0);
        *(float4*)(b + 4) = *(const float4*)(be2 + col0 + 4);
        float cs[8], cq[8];
#pragma unroll
        for (int j = 0; j < 8; j++) { cs[j] = 0.f; cq[j] = 0.f; }
#pragma unroll
        for (int i = 0; i < 8; i++) {
            float mv[8];
#pragma unroll
            for (int jp = 0; jp < 4; jp++) {
                float2 c = unpk(acc[i][jp]);
                mv[2 * jp]     = silu_f(c.x + b[2 * jp]);
                mv[2 * jp + 1] = silu_f(c.y + b[2 * jp + 1]);
            }
            const int d = dsts[row0 + i];
            red_add_v4(&g_mi[(size_t)d * 128 + col0],
                       make_float4(mv[0], mv[1], mv[2], mv[3]));
            red_add_v4(&g_mi[(size_t)d * 128 + col0 + 4],
                       make_float4(mv[4], mv[5], mv[6], mv[7]));
            if (write_mij) {
                float* gp = g_mij + (size_t)(m0 + row0 + i) * 128 + col0;
                *(float4*)gp       = make_float4(mv[0], mv[1], mv[2], mv[3]);
                *(float4*)(gp + 4) = make_float4(mv[4], mv[5], mv[6], mv[7]);
#pragma unroll
                for (int j = 0; j < 8; j++) {
                    float e = elu_f(mv[j]);
                    cs[j] += e;
                    cq[j] += e * e;
                }
            }
            float* trow = Ts + ts_off(row0 + i, col0);
            *(float4*)trow       = make_float4(mv[0], mv[1], mv[2], mv[3]);
            *(float4*)(trow + 4) = make_float4(mv[4], mv[5], mv[6], mv[7]);
        }
        if (write_mij) {
#pragma unroll
            for (int j = 0; j < 8; j++) {
                atomicAdd(&es[col0 + j], cs[j]);
                atomicAdd(&es[128 + col0 + j], cq[j]);
            }
        }
    }
    __syncthreads();
    if (write_mij && tid < 128) {
        g_partE[blockIdx.x * 128 + tid] = es[tid];
        g_partE[(EDGE_TILES + blockIdx.x) * 128 + tid] = es[128 + tid];
    }

    // T2 = silu(mij @ Wx1 + bx1)
#pragma unroll
    for (int i = 0; i < 8; i++)
#pragma unroll
        for (int j = 0; j < 4; j++) acc[i][j] = 0ULL;
    {
        float vb[8];
        loadB8(Wx1, brow, vb); storeB(0, vb);
    }
    __syncthreads();
    buf = 0;
    for (int kt = 0; kt < 8; kt++) {
        float nb[8];
        const bool pre = (kt < 7);
        if (pre) loadB8(Wx1, (kt + 1) * 16 + brow, nb);
        gemm_tile(acc, Ts, Bs + buf * 2112, kt * 16, row0, col0);
        if (pre) storeB(buf ^ 1, nb);
        __syncthreads();
        buf ^= 1;
    }
    {
        float b[8];
        *(float4*)b       = *(const float4*)(bx1 + col0);
        *(float4*)(b + 4) = *(const float4*)(bx1 + col0 + 4);
#pragma unroll
        for (int i = 0; i < 8; i++) {
            float* trow = Ts + ts_off(row0 + i, col0);
#pragma unroll
            for (int jp = 0; jp < 4; jp++) {
                float2 c = unpk(acc[i][jp]);
                trow[2 * jp]     = silu_f(c.x + b[2 * jp]);
                trow[2 * jp + 1] = silu_f(c.y + b[2 * jp + 1]);
            }
        }
    }
    __syncthreads();

    // px = T2 @ Wx2 + bx2 ; coord scatter
    if (tid < 128) {
        const float* trow = Ts + ts_off(tid, 0);
        float p0 = 0.f, p1 = 0.f, p2 = 0.f;
#pragma unroll 8
        for (int k = 0; k < 128; k++) {
            float t = trow[k];
            p0 += t * wx2s[k * 3 + 0];
            p1 += t * wx2s[k * 3 + 1];
            p2 += t * wx2s[k * 3 + 2];
        }
        p0 += bx2s[0]; p1 += bx2s[1]; p2 += bx2s[2];
        const int d = dsts[tid];
        atomicAdd(&g_accum[d * 3 + 0], diffs[tid * 3 + 0] * p0);
        atomicAdd(&g_accum[d * 3 + 1], diffs[tid * 3 + 1] * p1);
        atomicAdd(&g_accum[d * 3 + 2], diffs[tid * 3 + 2] * p2);
    }
}

// ---------------- proj_k: [Ps|Pd] = V @ [We1a|We1b], BM=64, N=256 ----------
// Also zeros g_mi / g_accum for its 64 nodes.
__global__ __launch_bounds__(256) void proj_k(
    const float* __restrict__ V, const float* __restrict__ We1l,
    float* __restrict__ Ps, float* __restrict__ Pd, int M)
{
    __shared__ float As[16][68];
    __shared__ float Bs[16][264];

    const int tid  = threadIdx.x;
    const int m0   = blockIdx.x * 64;
    const int arow = tid >> 2;          // 0..63
    const int akb  = (tid & 3) * 4;
    const int brow = tid >> 4;          // 0..15
    const int bcol = (tid & 15) * 16;   // 0..240
    const int gm   = m0 + arow;
    const bool mval = (gm < M);
    const int row0 = (tid >> 4) * 4;
    const int col0 = (tid & 15) * 16;

    // zero mi rows and accum for this CTA's nodes
    {
        int r = tid >> 2, c = (tid & 3) * 32;   // 64 rows x 128 cols, 32/thread
        if (m0 + r < M) {
            float4 z = make_float4(0.f, 0.f, 0.f, 0.f);
            float* p = g_mi + (size_t)(m0 + r) * 128 + c;
#pragma unroll
            for (int j = 0; j < 8; j++) *(float4*)(p + j * 4) = z;
        }
        if (tid < 192 && m0 + tid / 3 < M)
            g_accum[(size_t)m0 * 3 + tid] = 0.f;
    }

    float acc[4][16];
#pragma unroll
    for (int i = 0; i < 4; i++)
#pragma unroll
        for (int j = 0; j < 16; j++) acc[i][j] = 0.f;

    for (int kt = 0; kt < 8; kt++) {
        const int kbase = kt * 16;
        // B tile: cols 0..127 from We1 rows [k], cols 128..255 from rows [128+k]
        {
            const int gk = kbase + brow;
            const float* wp = (bcol < 128)
                ? We1l + (size_t)gk * 128 + bcol
                : We1l + (size_t)(128 + gk) * 128 + (bcol - 128);
#pragma unroll
            for (int j = 0; j < 16; j += 4)
                *(float4*)&Bs[brow][bcol + j] = *(const float4*)(wp + j);
        }
#pragma unroll
        for (int i = 0; i < 4; i++) {
            const int gk = kbase + akb + i;
            As[akb + i][arow] = mval ? V[(size_t)gm * 128 + gk] : 0.f;
        }
        __syncthreads();
#pragma unroll
        for (int kk = 0; kk < 16; kk++) {
            float4 a = *(const float4*)&As[kk][row0];
            float av[4] = {a.x, a.y, a.z, a.w};
            float bv[16];
#pragma unroll
            for (int j = 0; j < 16; j += 4)
                *(float4*)&bv[j] = *(const float4*)&Bs[kk][col0 + j];
#pragma unroll
            for (int i = 0; i < 4; i++)
#pragma unroll
                for (int j = 0; j < 16; j++) acc[i][j] += av[i] * bv[j];
        }
        __syncthreads();
    }

#pragma unroll
    for (int i = 0; i < 4; i++) {
        const int mm = m0 + row0 + i;
        if (mm < M) {
            float* cp = (col0 < 128)
                ? Ps + (size_t)mm * 128 + col0
                : Pd + (size_t)mm * 128 + (col0 - 128);
#pragma unroll
            for (int j = 0; j < 16; j += 4)
                *(float4*)(cp + j) = *(float4*)&acc[i][j];
        }
    }
}

// ---------------- node_fused_k: VH=silu([V,mi]@Wh1+bh1) (smem);
//                  Vraw=VH@Wh2+bh2 (+BN stats) -------------------------------
__global__ __launch_bounds__(256) void node_fused_k(
    const float* __restrict__ V, const float* __restrict__ mi,
    const float* __restrict__ Wh1, const float* __restrict__ bh1,
    const float* __restrict__ Wh2, const float* __restrict__ bh2,
    float* __restrict__ Vraw, float* __restrict__ part, int M, int nblk)
{
    __shared__ float VH[64 * 132 + 4];   // swizzled 64x128 tile
    __shared__ float As[16][68];
    __shared__ float Bs[16][132];
    __shared__ float sstat[256];

    const int tid  = threadIdx.x;
    const int m0   = blockIdx.x * 64;
    const int arow = tid >> 2;
    const int akb  = (tid & 3) * 4;
    const int brow = tid >> 4;
    const int bcol = (tid & 15) * 8;
    const int gm   = m0 + arow;
    const bool mval = (gm < M);
    const int row0 = (tid >> 4) * 4;
    const int col0 = (tid & 15) * 8;

    sstat[tid] = 0.f;

    // ---- phase A: VH = silu([V, mi] @ Wh1 + bh1), K=256 ----
    float accA[4][8];
#pragma unroll
    for (int i = 0; i < 4; i++)
#pragma unroll
        for (int j = 0; j < 8; j++) accA[i][j] = 0.f;

    for (int kt = 0; kt < 16; kt++) {
        const int kbase = kt * 16;
        {
            const float* wp = Wh1 + (size_t)(kbase + brow) * 128 + bcol;
#pragma unroll
            for (int j = 0; j < 8; j += 4)
                *(float4*)&Bs[brow][bcol + j] = *(const float4*)(wp + j);
        }
#pragma unroll
        for (int i = 0; i < 4; i++) {
            const int gk = kbase + akb + i;
            float v = 0.f;
            if (mval)
                v = (gk < 128) ? V[(size_t)gm * 128 + gk]
                               : mi[(size_t)gm * 128 + (gk - 128)];
            As[akb + i][arow] = v;
        }
        __syncthreads();
#pragma unroll
        for (int kk = 0; kk < 16; kk++) {
            float4 a = *(const float4*)&As[kk][row0];
            float4 b0 = *(const float4*)&Bs[kk][col0];
            float4 b1 = *(const float4*)&Bs[kk][col0 + 4];
            float av[4] = {a.x, a.y, a.z, a.w};
            float bv[8] = {b0.x, b0.y, b0.z, b0.w, b1.x, b1.y, b1.z, b1.w};
#pragma unroll
            for (int i = 0; i < 4; i++)
#pragma unroll
                for (int j = 0; j < 8; j++) accA[i][j] += av[i] * bv[j];
        }
        __syncthreads();
    }
    {
        float b[8];
        *(float4*)b       = *(const float4*)(bh1 + col0);
        *(float4*)(b + 4) = *(const float4*)(bh1 + col0 + 4);
#pragma unroll
        for (int i = 0; i < 4; i++) {
            float* trow = VH + ts_off(row0 + i, col0);
            float o[8];
#pragma unroll
            for (int j = 0; j < 8; j++) o[j] = silu_f(accA[i][j] + b[j]);
            *(float4*)trow       = *(float4*)&o[0];
            *(float4*)(trow + 4) = *(float4*)&o[4];
        }
    }
    __syncthreads();

    // ---- phase B: Vraw = VH @ Wh2 + bh2, K=128, + BN stats ----
    ull acc[4][4];
#pragma unroll
    for (int i = 0; i < 4; i++)
#pragma unroll
        for (int j = 0; j < 4; j++) acc[i][j] = 0ULL;

    for (int kt = 0; kt < 8; kt++) {
        const int kbase = kt * 16;
        {
            const float* wp = Wh2 + (size_t)(kbase + brow) * 128 + bcol;
#pragma unroll
            for (int j = 0; j < 8; j += 4)
                *(float4*)&Bs[brow][bcol + j] = *(const float4*)(wp + j);
        }
        __syncthreads();
        gemm_tile4(acc, VH, &Bs[0][0], kbase, row0, col0);
        __syncthreads();
    }
    {
        float b[8];
        *(float4*)b       = *(const float4*)(bh2 + col0);
        *(float4*)(b + 4) = *(const float4*)(bh2 + col0 + 4);
        float cs[8], cq[8];
#pragma unroll
        for (int j = 0; j < 8; j++) { cs[j] = 0.f; cq[j] = 0.f; }
#pragma unroll
        for (int i = 0; i < 4; i++) {
            const int mm = m0 + row0 + i;
            if (mm < M) {
                float o[8];
#pragma unroll
                for (int jp = 0; jp < 4; jp++) {
                    float2 c = unpk(acc[i][jp]);
                    o[2 * jp]     = c.x + b[2 * jp];
                    o[2 * jp + 1] = c.y + b[2 * jp + 1];
                }
                float* cp = Vraw + (size_t)mm * 128 + col0;
                *(float4*)cp       = *(float4*)&o[0];
                *(float4*)(cp + 4) = *(float4*)&o[4];
#pragma unroll
                for (int j = 0; j < 8; j++) {
                    float e = elu_f(o[j]);
                    cs[j] += e;
                    cq[j] += e * e;
                }
            }
        }
        __syncthreads();
#pragma unroll
        for (int j = 0; j < 8; j++) {
            atomicAdd(&sstat[col0 + j], cs[j]);
            atomicAdd(&sstat[128 + col0 + j], cq[j]);
        }
        __syncthreads();
        if (tid < 128) {
            part[blockIdx.x * 128 + tid] = sstat[tid];
            part[(nblk + blockIdx.x) * 128 + tid] = sstat[128 + tid];
        }
    }
}

// ---------------- small kernels ----------------
__global__ void init_nodes_k(const float* __restrict__ emb,
                             const float* __restrict__ Wn,
                             const float* __restrict__ bn)
{
    int idx = blockIdx.x * blockDim.x + threadIdx.x;
    if (idx < N_NODES * 3) g_coords[idx] = emb[idx];
    if (idx < N_NODES * HDIM) {
        int n = idx >> 7, j = idx & 127;
        g_V[idx] = emb[n * 3 + 0] * Wn[0 * 128 + j]
                 + emb[n * 3 + 1] * Wn[1 * 128 + j]
                 + emb[n * 3 + 2] * Wn[2 * 128 + j]
                 + bn[j];
    }
}

__global__ void coords_update_k()
{
    int idx = blockIdx.x * blockDim.x + threadIdx.x;
    if (idx < N_NODES * 3)
        g_coords[idx] += g_accum[idx] * (1.0f / (float)(N_NODES - 1));
}

// ---------------- BatchNorm finalize ----------------
__global__ void bn_stats2_k(const float* __restrict__ part, int B, int M)
{
    int j = threadIdx.x;
    double s = 0.0, q = 0.0;
    for (int b = 0; b < B; b++) {
        s += (double)part[b * 128 + j];
        q += (double)part[(B + b) * 128 + j];
    }
    double mu  = s / (double)M;
    double var = q / (double)M - mu * mu;
    g_muinv[j]       = (float)mu;
    g_muinv[128 + j] = (float)rsqrt(var + (double)BN_EPS);
}

__global__ void bn_norm_k(const float* __restrict__ X,
                          const float* __restrict__ gam,
                          const float* __restrict__ bet,
                          float* __restrict__ out, int M)
{
    int idx = blockIdx.x * blockDim.x + threadIdx.x;
    if (idx >= M * 128) return;
    int j = idx & 127;
    float x = elu_f(X[idx]);
    out[idx] = gam[j] * (x - g_muinv[j]) * g_muinv[128 + j] + bet[j];
}

// ---------------- host launcher ----------------
static void* sym_addr(const void* sym)
{
    void* p = nullptr;
    cudaGetSymbolAddress(&p, sym);
    return p;
}

extern "C" void kernel_launch(void* const* d_in, const int* in_sizes, int n_in,
                              void* d_out, int out_size)
{
    (void)in_sizes; (void)n_in; (void)out_size;

    const float* emb_nodes = (const float*)d_in[0];
    const float* emb_edges = (const float*)d_in[1];
    const int*   edge_idx  = (const int*)d_in[2];
    const float* pre_Wn    = (const float*)d_in[3];
    const float* pre_bn    = (const float*)d_in[4];
    const float* We1 = (const float*)d_in[7];
    const float* be1 = (const float*)d_in[8];
    const float* We2 = (const float*)d_in[9];
    const float* be2 = (const float*)d_in[10];
    const float* Wx1 = (const float*)d_in[11];
    const float* bx1 = (const float*)d_in[12];
    const float* Wx2 = (const float*)d_in[13];
    const float* bx2 = (const float*)d_in[14];
    const float* Wh1 = (const float*)d_in[15];
    const float* bh1 = (const float*)d_in[16];
    const float* Wh2 = (const float*)d_in[17];
    const float* bh2 = (const float*)d_in[18];
    const float* gam_n = (const float*)d_in[19];
    const float* bet_n = (const float*)d_in[20];
    const float* gam_e = (const float*)d_in[21];
    const float* bet_e = (const float*)d_in[22];

    float* out  = (float*)d_out;
    float* outV = out;
    float* outE = out + (size_t)N_NODES * HDIM;

    const int* srcv = edge_idx;
    const int* dstv = edge_idx + N_EDGES;

    float* pV     = (float*)sym_addr(g_V);
    float* pVraw  = (float*)sym_addr(g_Vraw);
    float* pVH    = (float*)sym_addr(g_VH);
    float* pMi    = (float*)sym_addr(g_mi);
    float* pMij   = (float*)sym_addr(g_mij);
    float* pPartE = (float*)sym_addr(g_partE);
    float* pPartN = (float*)sym_addr(g_partN);

    const int EDGE_SMEM = 23172 * 4;
    cudaFuncSetAttribute(edge_fused_k,
                         cudaFuncAttributeMaxDynamicSharedMemorySize, EDGE_SMEM);

    const int TB = 256;
    const int nodeHBlocks = (N_NODES * HDIM + TB - 1) / TB;
    const int edgeHBlocks = (N_EDGES * HDIM + TB - 1) / TB;

    init_nodes_k<<<nodeHBlocks, TB>>>(emb_nodes, pre_Wn, pre_bn);

    for (int l = 0; l < NLAYERS; l++) {
        const float* We1l = We1 + (size_t)l * 259 * 128;
        const float* be1l = be1 + l * 128;
        const float* We2l = We2 + (size_t)l * 128 * 128;
        const float* be2l = be2 + l * 128;
        const float* Wx1l = Wx1 + (size_t)l * 128 * 128;
        const float* bx1l = bx1 + l * 128;
        const float* Wx2l = Wx2 + (size_t)l * 128 * 3;
        const float* bx2l = bx2 + l * 3;
        const float* Wh1l = Wh1 + (size_t)l * 256 * 128;
        const float* bh1l = bh1 + l * 128;
        const float* Wh2l = Wh2 + (size_t)l * 128 * 128;
        const float* bh2l = bh2 + l * 128;

        // Ps -> g_VH, Pd -> g_Vraw ; also zeros g_mi / g_accum
        proj_k<<<NODE_TILES, 256>>>(pV, We1l, pVH, pVraw, N_NODES);

        edge_fused_k<<<EDGE_TILES, 256, EDGE_SMEM>>>(
            srcv, dstv, emb_edges, pVH, pVraw,
            We1l + 256 * 128, be1l,
            We2l, be2l, Wx1l, bx1l, Wx2l, bx2l,
            (l == NLAYERS - 1) ? 1 : 0);

        coords_update_k<<<(N_NODES * 3 + TB - 1) / TB, TB>>>();

        node_fused_k<<<NODE_TILES, 256>>>(
            pV, pMi, Wh1l, bh1l, Wh2l, bh2l,
            pVraw, pPartN, N_NODES, NODE_TILES);

        bn_stats2_k<<<1, 128>>>(pPartN, NODE_TILES, N_NODES);
        float* vdst = (l == NLAYERS - 1) ? outV : pV;
        bn_norm_k<<<nodeHBlocks, TB>>>(pVraw, gam_n + l * 128, bet_n + l * 128,
                                       vdst, N_NODES);

        if (l == NLAYERS - 1) {
            bn_stats2_k<<<1, 128>>>(pPartE, EDGE_TILES, N_EDGES);
            bn_norm_k<<<edgeHBlocks, TB>>>(pMij, gam_e + l * 128, bet_e + l * 128,
                                           outE, N_EDGES);
        }
    }
}

// round 8
// speedup vs baseline: 1.0660x; 1.0660x over previous
#include <cuda_runtime.h>
#include <cuda_bf16.h>
#include <math.h>
#include <stdint.h>

typedef unsigned long long ull;

#define N_NODES 10000
#define N_EDGES 160000
#define HDIM    128
#define NLAYERS 3
#define BN_EPS  1e-5f

#define EDGE_TILES (N_EDGES / 128)        // 1250
#define NODE_TILES ((N_NODES + 63) / 64)  // 157

// bf16 tile geometry: 128 rows x 128 cols, row stride 136 bf16 (272 B)
#define TROW 272
#define TILE_BYTES (128 * TROW)           // 34816

// ---------------- device scratch ----------------
__device__ float g_coords[N_NODES * 3];
__device__ float g_V[N_NODES * HDIM];
__device__ float g_Vraw[N_NODES * HDIM];   // Pd during edge phase
__device__ float g_VH[N_NODES * HDIM];     // Ps during edge phase
__device__ float g_mi[N_NODES * HDIM];
__device__ float g_accum[N_NODES * 3];
__device__ float g_mij[N_EDGES * HDIM];
__device__ float g_partE[2 * EDGE_TILES * HDIM];
__device__ float g_partN[2 * 160 * HDIM];
__device__ float g_muinv[2 * HDIM];
// bf16 weight images, [layer][mat(We2t,Wx1t)][n*128+k] (row-major [n][k])
__device__ __nv_bfloat16 g_wbhi[NLAYERS * 2 * 16384];
__device__ __nv_bfloat16 g_wblo[NLAYERS * 2 * 16384];

__device__ __forceinline__ float silu_f(float x) { return x / (1.0f + expf(-x)); }
__device__ __forceinline__ float elu_f(float x)  { return x > 0.0f ? x : (expf(x) - 1.0f); }

__device__ __forceinline__ ull fma2(ull a, ull b, ull c) {
    ull d;
    asm("fma.rn.f32x2 %0, %1, %2, %3;" : "=l"(d) : "l"(a), "l"(b), "l"(c));
    return d;
}
__device__ __forceinline__ float2 unpk(ull v) {
    unsigned lo, hi;
    asm("mov.b64 {%0,%1}, %2;" : "=r"(lo), "=r"(hi) : "l"(v));
    return make_float2(__uint_as_float(lo), __uint_as_float(hi));
}
__device__ __forceinline__ ull dup2(float a) {
    ull d;
    asm("mov.b64 %0, {%1,%1};" : "=l"(d) : "f"(a));
    return d;
}
__device__ __forceinline__ void red_add_v2(float* addr, float x, float y) {
    asm volatile("red.global.add.v2.f32 [%0], {%1,%2};"
                 :: "l"(addr), "f"(x), "f"(y) : "memory");
}

__device__ __forceinline__ uint32_t pk_bf2(float x, float y) {
    __nv_bfloat162 t = __floats2bfloat162_rn(x, y);
    return *(uint32_t*)&t;
}
__device__ __forceinline__ float bf_hi(float x) {
    return __bfloat162float(__float2bfloat16(x));
}

// mma.sync m16n8k16 bf16 (plain PTX; compiles for compute_103)
__device__ __forceinline__ void mma16816(float* d, uint32_t a0, uint32_t a1,
                                         uint32_t a2, uint32_t a3,
                                         uint32_t b0, uint32_t b1) {
    asm("mma.sync.aligned.m16n8k16.row.col.f32.bf16.bf16.f32 "
        "{%0,%1,%2,%3}, {%4,%5,%6,%7}, {%8,%9}, {%0,%1,%2,%3};"
        : "+f"(d[0]), "+f"(d[1]), "+f"(d[2]), "+f"(d[3])
        : "r"(a0), "r"(a1), "r"(a2), "r"(a3), "r"(b0), "r"(b1));
}

// warp GEMM: acc[nt][4] = A[warp rows 16][128] @ Bt[n][k]^T, bf16 split-3
// abase/bbase: per-lane byte offsets (row*TROW + q*4) into the tiles
__device__ __forceinline__ void warp_gemm3(float (&acc)[16][4],
                                           const char* Ah, const char* Al,
                                           const char* Bh, const char* Bl,
                                           int abase, int bbase)
{
#pragma unroll
    for (int i = 0; i < 16; i++)
#pragma unroll
        for (int j = 0; j < 4; j++) acc[i][j] = 0.f;

#pragma unroll 1
    for (int sp = 0; sp < 3; sp++) {
        const char* A = (sp == 1) ? Al : Ah;
        const char* B = (sp == 2) ? Bl : Bh;
#pragma unroll 2
        for (int ks = 0; ks < 8; ks++) {
            const char* ap = A + abase + ks * 32;
            uint32_t a0 = *(const uint32_t*)(ap);
            uint32_t a2 = *(const uint32_t*)(ap + 16);
            uint32_t a1 = *(const uint32_t*)(ap + 8 * TROW);
            uint32_t a3 = *(const uint32_t*)(ap + 8 * TROW + 16);
            const char* bp = B + bbase + ks * 32;
#pragma unroll
            for (int nt = 0; nt < 16; nt++) {
                uint32_t b0 = *(const uint32_t*)(bp + nt * 8 * TROW);
                uint32_t b1 = *(const uint32_t*)(bp + nt * 8 * TROW + 16);
                mma16816(acc[nt], a0, a1, a2, a3, b0, b1);
            }
        }
    }
}

// ---------------- weight pre-convert: W[k][n] f32 -> bf16 hi/lo [n][k] ------
__global__ void convw_k(const float* __restrict__ We2, const float* __restrict__ Wx1)
{
    int idx = blockIdx.x * 256 + threadIdx.x;
    if (idx >= NLAYERS * 2 * 16384) return;
    int l = idx / 32768;
    int rest = idx % 32768;
    int m = rest >> 14;
    int e = rest & 16383;
    int n = e >> 7, k = e & 127;
    const float* W = m ? (Wx1 + (size_t)l * 16384) : (We2 + (size_t)l * 16384);
    float x = W[k * 128 + n];
    __nv_bfloat16 h = __float2bfloat16(x);
    __nv_bfloat16 lo = __float2bfloat16(x - __bfloat162float(h));
    g_wbhi[(l * 2 + m) * 16384 + n * 128 + k] = h;
    g_wblo[(l * 2 + m) * 16384 + n * 128 + k] = lo;
}

// ---------------- fused edge pipeline (mma.sync tensor path) ----------------
__global__ __launch_bounds__(256)
void edge_mma_k(const int* __restrict__ srcv, const int* __restrict__ dstv,
                const float* __restrict__ ee,
                const float* __restrict__ Ps, const float* __restrict__ Pd,
                const float* __restrict__ wex_g, const float* __restrict__ be1,
                const float* __restrict__ be2, const float* __restrict__ bx1,
                const float* __restrict__ Wx2, const float* __restrict__ bx2,
                const __nv_bfloat16* __restrict__ WBhi,
                const __nv_bfloat16* __restrict__ WBlo,
                int write_mij)
{
    extern __shared__ char smc[];
    float* smf = (float*)smc;
    float* diffs = smf + 0;      // 384
    float* dists = smf + 384;    // 128
    int*   dsts  = (int*)(smf + 512);
    float* ee0s  = smf + 640;
    float* ee1s  = smf + 768;
    float* wex   = smf + 896;    // 384
    float* be1s  = smf + 1280;
    float* be2s  = smf + 1408;
    float* bx1s  = smf + 1536;
    float* wx2s  = smf + 1664;   // 384
    float* bx2s  = smf + 2048;   // 4
    float* es    = smf + 2052;   // 256
    char* Ah  = smc + 9248;
    char* Al  = Ah  + TILE_BYTES;
    char* Bh1 = Al  + TILE_BYTES;
    char* Bl1 = Bh1 + TILE_BYTES;
    char* Bh2 = Bl1 + TILE_BYTES;
    char* Bl2 = Bh2 + TILE_BYTES;

    const int tid  = threadIdx.x;
    const int wid  = tid >> 5;
    const int lane = tid & 31;
    const int g    = lane >> 2;
    const int q    = lane & 3;
    const int m0   = blockIdx.x * 128;

    // ---- phase 0: geometry, biases, weight tiles ----
    if (tid < 128) {
        int mm = m0 + tid;
        int s = srcv[mm], d = dstv[mm];
        float dx = g_coords[d * 3 + 0] - g_coords[s * 3 + 0];
        float dy = g_coords[d * 3 + 1] - g_coords[s * 3 + 1];
        float dz = g_coords[d * 3 + 2] - g_coords[s * 3 + 2];
        diffs[tid * 3 + 0] = dx;
        diffs[tid * 3 + 1] = dy;
        diffs[tid * 3 + 2] = dz;
        dists[tid] = sqrtf(dx * dx + dy * dy + dz * dz);
        dsts[tid] = d;
        ee0s[tid] = ee[mm * 2 + 0];
        ee1s[tid] = ee[mm * 2 + 1];
        be1s[tid] = be1[tid];
        be2s[tid] = be2[tid];
        bx1s[tid] = bx1[tid];
    }
    es[tid] = 0.f;
    for (int i = tid; i < 384; i += 256) { wex[i] = wex_g[i]; wx2s[i] = Wx2[i]; }
    if (tid < 3) bx2s[tid] = bx2[tid];

    // copy 4 weight tiles (We2t hi/lo, Wx1t hi/lo) with stride padding
    {
        const char* srcs[4] = {(const char*)WBhi, (const char*)WBlo,
                               (const char*)(WBhi + 16384), (const char*)(WBlo + 16384)};
        char* dstp[4] = {Bh1, Bl1, Bh2, Bl2};
#pragma unroll
        for (int t = 0; t < 4; t++) {
            const uint4* s4 = (const uint4*)srcs[t];
            char* d4 = dstp[t];
#pragma unroll
            for (int i = 0; i < 8; i++) {
                int p = tid + i * 256;       // 0..2047
                int row = p >> 4, chunk = p & 15;
                *(uint4*)(d4 + row * TROW + chunk * 16) = s4[p];
            }
        }
    }
    // REQUIRED: T1 build below reads wex/be1s written cooperatively above.
    __syncthreads();

    // ---- T1 build: silu(Ps[src]+Pd[dst]+dist*w+ee@W+be1) -> Ah/Al ----
    {
        const int r  = tid >> 1;
        const int cb = (tid & 1) * 64;
        const int mm = m0 + r;
        const int s  = srcv[mm];
        const float* psp = Ps + (size_t)s * 128;
        const float* pdp = Pd + (size_t)dsts[r] * 128;
        const float di = dists[r];
        const float e0 = ee0s[r], e1 = ee1s[r];
        for (int c = cb; c < cb + 64; c += 8) {
            float o[8];
#pragma unroll
            for (int h = 0; h < 8; h += 4) {
                float4 a = *(const float4*)(psp + c + h);
                float4 b = *(const float4*)(pdp + c + h);
                o[h+0] = silu_f(a.x + b.x + di * wex[c+h+0] + e0 * wex[128+c+h+0] + e1 * wex[256+c+h+0] + be1s[c+h+0]);
                o[h+1] = silu_f(a.y + b.y + di * wex[c+h+1] + e0 * wex[128+c+h+1] + e1 * wex[256+c+h+1] + be1s[c+h+1]);
                o[h+2] = silu_f(a.z + b.z + di * wex[c+h+2] + e0 * wex[128+c+h+2] + e1 * wex[256+c+h+2] + be1s[c+h+2]);
                o[h+3] = silu_f(a.w + b.w + di * wex[c+h+3] + e0 * wex[128+c+h+3] + e1 * wex[256+c+h+3] + be1s[c+h+3]);
            }
            uint32_t H[4], L[4];
#pragma unroll
            for (int j = 0; j < 4; j++) {
                float hx = bf_hi(o[2*j]), hy = bf_hi(o[2*j+1]);
                H[j] = pk_bf2(o[2*j], o[2*j+1]);
                L[j] = pk_bf2(o[2*j] - hx, o[2*j+1] - hy);
            }
            *(uint4*)(Ah + r * TROW + c * 2) = *(uint4*)H;
            *(uint4*)(Al + r * TROW + c * 2) = *(uint4*)L;
        }
    }
    __syncthreads();

    const int abase = (wid * 16 + g) * TROW + q * 4;
    const int bbase = g * TROW + q * 4;
    const int r0 = wid * 16 + g, r1 = r0 + 8;

    float acc[16][4];

    // ---- GEMM1: D = T1 @ We2t^T ----
    warp_gemm3(acc, Ah, Al, Bh1, Bl1, abase, bbase);

    // ---- epilogue 1: mij = silu(D + be2); mi scatter; mij/stats; A := mij --
    {
        const int d0 = dsts[r0], d1 = dsts[r1];
#pragma unroll
        for (int nt = 0; nt < 16; nt++) {
            const int c = nt * 8 + q * 2;
            float v00 = silu_f(acc[nt][0] + be2s[c]);
            float v01 = silu_f(acc[nt][1] + be2s[c + 1]);
            float v10 = silu_f(acc[nt][2] + be2s[c]);
            float v11 = silu_f(acc[nt][3] + be2s[c + 1]);
            red_add_v2(&g_mi[(size_t)d0 * 128 + c], v00, v01);
            red_add_v2(&g_mi[(size_t)d1 * 128 + c], v10, v11);
            if (write_mij) {
                *(float2*)(g_mij + (size_t)(m0 + r0) * 128 + c) = make_float2(v00, v01);
                *(float2*)(g_mij + (size_t)(m0 + r1) * 128 + c) = make_float2(v10, v11);
                float e00 = elu_f(v00), e01 = elu_f(v01);
                float e10 = elu_f(v10), e11 = elu_f(v11);
                float s0 = e00 + e10, s1 = e01 + e11;
                float q0 = e00 * e00 + e10 * e10, q1 = e01 * e01 + e11 * e11;
#pragma unroll
                for (int o = 4; o < 32; o <<= 1) {
                    s0 += __shfl_xor_sync(0xFFFFFFFF, s0, o);
                    s1 += __shfl_xor_sync(0xFFFFFFFF, s1, o);
                    q0 += __shfl_xor_sync(0xFFFFFFFF, q0, o);
                    q1 += __shfl_xor_sync(0xFFFFFFFF, q1, o);
                }
                if (lane < 4) {
                    atomicAdd(&es[c], s0);
                    atomicAdd(&es[c + 1], s1);
                    atomicAdd(&es[128 + c], q0);
                    atomicAdd(&es[128 + c + 1], q1);
                }
            }
            // rewrite warp-own A rows with mij hi/lo
            float h00 = bf_hi(v00), h01 = bf_hi(v01);
            float h10 = bf_hi(v10), h11 = bf_hi(v11);
            *(uint32_t*)(Ah + r0 * TROW + c * 2) = pk_bf2(v00, v01);
            *(uint32_t*)(Ah + r1 * TROW + c * 2) = pk_bf2(v10, v11);
            *(uint32_t*)(Al + r0 * TROW + c * 2) = pk_bf2(v00 - h00, v01 - h01);
            *(uint32_t*)(Al + r1 * TROW + c * 2) = pk_bf2(v10 - h10, v11 - h11);
        }
    }
    __syncwarp();   // make cross-lane A rewrites visible before GEMM2
    if (write_mij) {
        __syncthreads();
        if (tid < 128) {
            g_partE[blockIdx.x * 128 + tid] = es[tid];
            g_partE[(EDGE_TILES + blockIdx.x) * 128 + tid] = es[128 + tid];
        }
    }

    // ---- GEMM2: D = mij @ Wx1t^T  (A rows are warp-own) ----
    warp_gemm3(acc, Ah, Al, Bh2, Bl2, abase, bbase);

    // ---- epilogue 2: T2 = silu(D + bx1); px = T2 @ Wx2 + bx2; scatter ----
    {
        float pa0 = 0.f, pa1 = 0.f, pa2 = 0.f;
        float pb0 = 0.f, pb1 = 0.f, pb2 = 0.f;
#pragma unroll
        for (int nt = 0; nt < 16; nt++) {
            const int c = nt * 8 + q * 2;
            float t00 = silu_f(acc[nt][0] + bx1s[c]);
            float t01 = silu_f(acc[nt][1] + bx1s[c + 1]);
            float t10 = silu_f(acc[nt][2] + bx1s[c]);
            float t11 = silu_f(acc[nt][3] + bx1s[c + 1]);
            float w00 = wx2s[c * 3 + 0], w01 = wx2s[c * 3 + 1], w02 = wx2s[c * 3 + 2];
            float w10 = wx2s[c * 3 + 3], w11 = wx2s[c * 3 + 4], w12 = wx2s[c * 3 + 5];
            pa0 += t00 * w00 + t01 * w10;
            pa1 += t00 * w01 + t01 * w11;
            pa2 += t00 * w02 + t01 * w12;
            pb0 += t10 * w00 + t11 * w10;
            pb1 += t10 * w01 + t11 * w11;
            pb2 += t10 * w02 + t11 * w12;
        }
#pragma unroll
        for (int o = 1; o < 4; o <<= 1) {
            pa0 += __shfl_xor_sync(0xFFFFFFFF, pa0, o);
            pa1 += __shfl_xor_sync(0xFFFFFFFF, pa1, o);
            pa2 += __shfl_xor_sync(0xFFFFFFFF, pa2, o);
            pb0 += __shfl_xor_sync(0xFFFFFFFF, pb0, o);
            pb1 += __shfl_xor_sync(0xFFFFFFFF, pb1, o);
            pb2 += __shfl_xor_sync(0xFFFFFFFF, pb2, o);
        }
        if (q == 0) {
            const int d0 = dsts[r0], d1 = dsts[r1];
            float x0 = pa0 + bx2s[0], x1 = pa1 + bx2s[1], x2 = pa2 + bx2s[2];
            atomicAdd(&g_accum[d0 * 3 + 0], diffs[r0 * 3 + 0] * x0);
            atomicAdd(&g_accum[d0 * 3 + 1], diffs[r0 * 3 + 1] * x1);
            atomicAdd(&g_accum[d0 * 3 + 2], diffs[r0 * 3 + 2] * x2);
            float y0 = pb0 + bx2s[0], y1 = pb1 + bx2s[1], y2 = pb2 + bx2s[2];
            atomicAdd(&g_accum[d1 * 3 + 0], diffs[r1 * 3 + 0] * y0);
            atomicAdd(&g_accum[d1 * 3 + 1], diffs[r1 * 3 + 1] * y1);
            atomicAdd(&g_accum[d1 * 3 + 2], diffs[r1 * 3 + 2] * y2);
        }
    }
}

// ---------------- node side (unchanged from R5) ----------------
__device__ __forceinline__ int ts_off(int r, int c) {
    return r * 132 + ((r >> 3) & 1) * 4 + c;
}

__device__ __forceinline__ void gemm_tile4(ull (&acc)[4][4], const float* Ts,
                                           const float* Bs, int kbase,
                                           int row0, int col0)
{
    const float* arow = Ts + row0 * 132 + ((row0 >> 3) & 1) * 4 + kbase;
#pragma unroll
    for (int kk = 0; kk < 16; kk += 2) {
        const float* bp0 = Bs + kk * 132 + col0;
        const float* bp1 = bp0 + 132;
        ulonglong2 b01a = *(const ulonglong2*)bp0;
        ulonglong2 b23a = *(const ulonglong2*)(bp0 + 4);
        ulonglong2 b01b = *(const ulonglong2*)bp1;
        ulonglong2 b23b = *(const ulonglong2*)(bp1 + 4);
#pragma unroll
        for (int i = 0; i < 4; i++) {
            float2 a2 = *(const float2*)&arow[i * 132 + kk];
            ull av0 = dup2(a2.x), av1 = dup2(a2.y);
            acc[i][0] = fma2(av0, b01a.x, acc[i][0]);
            acc[i][1] = fma2(av0, b01a.y, acc[i][1]);
            acc[i][2] = fma2(av0, b23a.x, acc[i][2]);
            acc[i][3] = fma2(av0, b23a.y, acc[i][3]);
            acc[i][0] = fma2(av1, b01b.x, acc[i][0]);
            acc[i][1] = fma2(av1, b01b.y, acc[i][1]);
            acc[i][2] = fma2(av1, b23b.x, acc[i][2]);
            acc[i][3] = fma2(av1, b23b.y, acc[i][3]);
        }
    }
}

__global__ __launch_bounds__(256) void proj_k(
    const float* __restrict__ V, const float* __restrict__ We1l,
    float* __restrict__ Ps, float* __restrict__ Pd, int M)
{
    __shared__ float As[16][68];
    __shared__ float Bs[16][264];

    const int tid  = threadIdx.x;
    const int m0   = blockIdx.x * 64;
    const int arow = tid >> 2;
    const int akb  = (tid & 3) * 4;
    const int brow = tid >> 4;
    const int bcol = (tid & 15) * 16;
    const int gm   = m0 + arow;
    const bool mval = (gm < M);
    const int row0 = (tid >> 4) * 4;
    const int col0 = (tid & 15) * 16;

    {
        int r = tid >> 2, c = (tid & 3) * 32;
        if (m0 + r < M) {
            float4 z = make_float4(0.f, 0.f, 0.f, 0.f);
            float* p = g_mi + (size_t)(m0 + r) * 128 + c;
#pragma unroll
            for (int j = 0; j < 8; j++) *(float4*)(p + j * 4) = z;
        }
        if (tid < 192 && m0 + tid / 3 < M)
            g_accum[(size_t)m0 * 3 + tid] = 0.f;
    }

    float acc[4][16];
#pragma unroll
    for (int i = 0; i < 4; i++)
#pragma unroll
        for (int j = 0; j < 16; j++) acc[i][j] = 0.f;

    for (int kt = 0; kt < 8; kt++) {
        const int kbase = kt * 16;
        {
            const int gk = kbase + brow;
            const float* wp = (bcol < 128)
                ? We1l + (size_t)gk * 128 + bcol
                : We1l + (size_t)(128 + gk) * 128 + (bcol - 128);
#pragma unroll
            for (int j = 0; j < 16; j += 4)
                *(float4*)&Bs[brow][bcol + j] = *(const float4*)(wp + j);
        }
#pragma unroll
        for (int i = 0; i < 4; i++) {
            const int gk = kbase + akb + i;
            As[akb + i][arow] = mval ? V[(size_t)gm * 128 + gk] : 0.f;
        }
        __syncthreads();
#pragma unroll
        for (int kk = 0; kk < 16; kk++) {
            float4 a = *(const float4*)&As[kk][row0];
            float av[4] = {a.x, a.y, a.z, a.w};
            float bv[16];
#pragma unroll
            for (int j = 0; j < 16; j += 4)
                *(float4*)&bv[j] = *(const float4*)&Bs[kk][col0 + j];
#pragma unroll
            for (int i = 0; i < 4; i++)
#pragma unroll
                for (int j = 0; j < 16; j++) acc[i][j] += av[i] * bv[j];
        }
        __syncthreads();
    }

#pragma unroll
    for (int i = 0; i < 4; i++) {
        const int mm = m0 + row0 + i;
        if (mm < M) {
            float* cp = (col0 < 128)
                ? Ps + (size_t)mm * 128 + col0
                : Pd + (size_t)mm * 128 + (col0 - 128);
#pragma unroll
            for (int j = 0; j < 16; j += 4)
                *(float4*)(cp + j) = *(float4*)&acc[i][j];
        }
    }
}

__global__ __launch_bounds__(256) void node_fused_k(
    const float* __restrict__ V, const float* __restrict__ mi,
    const float* __restrict__ Wh1, const float* __restrict__ bh1,
    const float* __restrict__ Wh2, const float* __restrict__ bh2,
    float* __restrict__ Vraw, float* __restrict__ part, int M, int nblk)
{
    __shared__ float VH[64 * 132 + 4];
    __shared__ float As[16][68];
    __shared__ float Bs[16][132];
    __shared__ float sstat[256];

    const int tid  = threadIdx.x;
    const int m0   = blockIdx.x * 64;
    const int arow = tid >> 2;
    const int akb  = (tid & 3) * 4;
    const int brow = tid >> 4;
    const int bcol = (tid & 15) * 8;
    const int gm   = m0 + arow;
    const bool mval = (gm < M);
    const int row0 = (tid >> 4) * 4;
    const int col0 = (tid & 15) * 8;

    sstat[tid] = 0.f;

    float accA[4][8];
#pragma unroll
    for (int i = 0; i < 4; i++)
#pragma unroll
        for (int j = 0; j < 8; j++) accA[i][j] = 0.f;

    for (int kt = 0; kt < 16; kt++) {
        const int kbase = kt * 16;
        {
            const float* wp = Wh1 + (size_t)(kbase + brow) * 128 + bcol;
#pragma unroll
            for (int j = 0; j < 8; j += 4)
                *(float4*)&Bs[brow][bcol + j] = *(const float4*)(wp + j);
        }
#pragma unroll
        for (int i = 0; i < 4; i++) {
            const int gk = kbase + akb + i;
            float v = 0.f;
            if (mval)
                v = (gk < 128) ? V[(size_t)gm * 128 + gk]
                               : mi[(size_t)gm * 128 + (gk - 128)];
            As[akb + i][arow] = v;
        }
        __syncthreads();
#pragma unroll
        for (int kk = 0; kk < 16; kk++) {
            float4 a = *(const float4*)&As[kk][row0];
            float4 b0 = *(const float4*)&Bs[kk][col0];
            float4 b1 = *(const float4*)&Bs[kk][col0 + 4];
            float av[4] = {a.x, a.y, a.z, a.w};
            float bv[8] = {b0.x, b0.y, b0.z, b0.w, b1.x, b1.y, b1.z, b1.w};
#pragma unroll
            for (int i = 0; i < 4; i++)
#pragma unroll
                for (int j = 0; j < 8; j++) accA[i][j] += av[i] * bv[j];
        }
        __syncthreads();
    }
    {
        float b[8];
        *(float4*)b       = *(const float4*)(bh1 + col0);
        *(float4*)(b + 4) = *(const float4*)(bh1 + col0 + 4);
#pragma unroll
        for (int i = 0; i < 4; i++) {
            float* trow = VH + ts_off(row0 + i, col0);
            float o[8];
#pragma unroll
            for (int j = 0; j < 8; j++) o[j] = silu_f(accA[i][j] + b[j]);
            *(float4*)trow       = *(float4*)&o[0];
            *(float4*)(trow + 4) = *(float4*)&o[4];
        }
    }
    __syncthreads();

    ull acc[4][4];
#pragma unroll
    for (int i = 0; i < 4; i++)
#pragma unroll
        for (int j = 0; j < 4; j++) acc[i][j] = 0ULL;

    for (int kt = 0; kt < 8; kt++) {
        const int kbase = kt * 16;
        {
            const float* wp = Wh2 + (size_t)(kbase + brow) * 128 + bcol;
#pragma unroll
            for (int j = 0; j < 8; j += 4)
                *(float4*)&Bs[brow][bcol + j] = *(const float4*)(wp + j);
        }
        __syncthreads();
        gemm_tile4(acc, VH, &Bs[0][0], kbase, row0, col0);
        __syncthreads();
    }
    {
        float b[8];
        *(float4*)b       = *(const float4*)(bh2 + col0);
        *(float4*)(b + 4) = *(const float4*)(bh2 + col0 + 4);
        float cs[8], cq[8];
#pragma unroll
        for (int j = 0; j < 8; j++) { cs[j] = 0.f; cq[j] = 0.f; }
#pragma unroll
        for (int i = 0; i < 4; i++) {
            const int mm = m0 + row0 + i;
            if (mm < M) {
                float o[8];
#pragma unroll
                for (int jp = 0; jp < 4; jp++) {
                    float2 c = unpk(acc[i][jp]);
                    o[2 * jp]     = c.x + b[2 * jp];
                    o[2 * jp + 1] = c.y + b[2 * jp + 1];
                }
                float* cp = Vraw + (size_t)mm * 128 + col0;
                *(float4*)cp       = *(float4*)&o[0];
                *(float4*)(cp + 4) = *(float4*)&o[4];
#pragma unroll
                for (int j = 0; j < 8; j++) {
                    float e = elu_f(o[j]);
                    cs[j] += e;
                    cq[j] += e * e;
                }
            }
        }
        __syncthreads();
#pragma unroll
        for (int j = 0; j < 8; j++) {
            atomicAdd(&sstat[col0 + j], cs[j]);
            atomicAdd(&sstat[128 + col0 + j], cq[j]);
        }
        __syncthreads();
        if (tid < 128) {
            part[blockIdx.x * 128 + tid] = sstat[tid];
            part[(nblk + blockIdx.x) * 128 + tid] = sstat[128 + tid];
        }
    }
}

// ---------------- small kernels ----------------
__global__ void init_nodes_k(const float* __restrict__ emb,
                             const float* __restrict__ Wn,
                             const float* __restrict__ bn)
{
    int idx = blockIdx.x * blockDim.x + threadIdx.x;
    if (idx < N_NODES * 3) g_coords[idx] = emb[idx];
    if (idx < N_NODES * HDIM) {
        int n = idx >> 7, j = idx & 127;
        g_V[idx] = emb[n * 3 + 0] * Wn[0 * 128 + j]
                 + emb[n * 3 + 1] * Wn[1 * 128 + j]
                 + emb[n * 3 + 2] * Wn[2 * 128 + j]
                 + bn[j];
    }
}

__global__ void coords_update_k()
{
    int idx = blockIdx.x * blockDim.x + threadIdx.x;
    if (idx < N_NODES * 3)
        g_coords[idx] += g_accum[idx] * (1.0f / (float)(N_NODES - 1));
}

__global__ void bn_stats2_k(const float* __restrict__ part, int B, int M)
{
    int j = threadIdx.x;
    double s = 0.0, q = 0.0;
    for (int b = 0; b < B; b++) {
        s += (double)part[b * 128 + j];
        q += (double)part[(B + b) * 128 + j];
    }
    double mu  = s / (double)M;
    double var = q / (double)M - mu * mu;
    g_muinv[j]       = (float)mu;
    g_muinv[128 + j] = (float)rsqrt(var + (double)BN_EPS);
}

__global__ void bn_norm_k(const float* __restrict__ X,
                          const float* __restrict__ gam,
                          const float* __restrict__ bet,
                          float* __restrict__ out, int M)
{
    int idx = blockIdx.x * blockDim.x + threadIdx.x;
    if (idx >= M * 128) return;
    int j = idx & 127;
    float x = elu_f(X[idx]);
    out[idx] = gam[j] * (x - g_muinv[j]) * g_muinv[128 + j] + bet[j];
}

// ---------------- host launcher ----------------
static void* sym_addr(const void* sym)
{
    void* p = nullptr;
    cudaGetSymbolAddress(&p, sym);
    return p;
}

extern "C" void kernel_launch(void* const* d_in, const int* in_sizes, int n_in,
                              void* d_out, int out_size)
{
    (void)in_sizes; (void)n_in; (void)out_size;

    const float* emb_nodes = (const float*)d_in[0];
    const float* emb_edges = (const float*)d_in[1];
    const int*   edge_idx  = (const int*)d_in[2];
    const float* pre_Wn    = (const float*)d_in[3];
    const float* pre_bn    = (const float*)d_in[4];
    const float* We1 = (const float*)d_in[7];
    const float* be1 = (const float*)d_in[8];
    const float* We2 = (const float*)d_in[9];
    const float* be2 = (const float*)d_in[10];
    const float* Wx1 = (const float*)d_in[11];
    const float* bx1 = (const float*)d_in[12];
    const float* Wx2 = (const float*)d_in[13];
    const float* bx2 = (const float*)d_in[14];
    const float* Wh1 = (const float*)d_in[15];
    const float* bh1 = (const float*)d_in[16];
    const float* Wh2 = (const float*)d_in[17];
    const float* bh2 = (const float*)d_in[18];
    const float* gam_n = (const float*)d_in[19];
    const float* bet_n = (const float*)d_in[20];
    const float* gam_e = (const float*)d_in[21];
    const float* bet_e = (const float*)d_in[22];

    float* out  = (float*)d_out;
    float* outV = out;
    float* outE = out + (size_t)N_NODES * HDIM;

    const int* srcv = edge_idx;
    const int* dstv = edge_idx + N_EDGES;

    float* pV     = (float*)sym_addr(g_V);
    float* pVraw  = (float*)sym_addr(g_Vraw);
    float* pVH    = (float*)sym_addr(g_VH);
    float* pMi    = (float*)sym_addr(g_mi);
    float* pMij   = (float*)sym_addr(g_mij);
    float* pPartE = (float*)sym_addr(g_partE);
    float* pPartN = (float*)sym_addr(g_partN);
    __nv_bfloat16* pWbhi = (__nv_bfloat16*)sym_addr(g_wbhi);
    __nv_bfloat16* pWblo = (__nv_bfloat16*)sym_addr(g_wblo);

    const int EDGE_SMEM = 9248 + 6 * TILE_BYTES;   // 218144 B
    cudaFuncSetAttribute(edge_mma_k,
                         cudaFuncAttributeMaxDynamicSharedMemorySize, EDGE_SMEM);

    const int TB = 256;
    const int nodeHBlocks = (N_NODES * HDIM + TB - 1) / TB;
    const int edgeHBlocks = (N_EDGES * HDIM + TB - 1) / TB;

    init_nodes_k<<<nodeHBlocks, TB>>>(emb_nodes, pre_Wn, pre_bn);
    convw_k<<<(NLAYERS * 2 * 16384 + 255) / 256, 256>>>(We2, Wx1);

    for (int l = 0; l < NLAYERS; l++) {
        const float* We1l = We1 + (size_t)l * 259 * 128;
        const float* be1l = be1 + l * 128;
        const float* be2l = be2 + l * 128;
        const float* bx1l = bx1 + l * 128;
        const float* Wx2l = Wx2 + (size_t)l * 128 * 3;
        const float* bx2l = bx2 + l * 3;
        const float* Wh1l = Wh1 + (size_t)l * 256 * 128;
        const float* bh1l = bh1 + l * 128;
        const float* Wh2l = Wh2 + (size_t)l * 128 * 128;
        const float* bh2l = bh2 + l * 128;

        proj_k<<<NODE_TILES, 256>>>(pV, We1l, pVH, pVraw, N_NODES);

        edge_mma_k<<<EDGE_TILES, 256, EDGE_SMEM>>>(
            srcv, dstv, emb_edges, pVH, pVraw,
            We1l + 256 * 128, be1l, be2l, bx1l, Wx2l, bx2l,
            pWbhi + (size_t)l * 2 * 16384, pWblo + (size_t)l * 2 * 16384,
            (l == NLAYERS - 1) ? 1 : 0);

        coords_update_k<<<(N_NODES * 3 + TB - 1) / TB, TB>>>();

        node_fused_k<<<NODE_TILES, 256>>>(
            pV, pMi, Wh1l, bh1l, Wh2l, bh2l,
            pVraw, pPartN, N_NODES, NODE_TILES);

        bn_stats2_k<<<1, 128>>>(pPartN, NODE_TILES, N_NODES);
        float* vdst = (l == NLAYERS - 1) ? outV : pV;
        bn_norm_k<<<nodeHBlocks, TB>>>(pVraw, gam_n + l * 128, bet_n + l * 128,
                                       vdst, N_NODES);

        if (l == NLAYERS - 1) {
            bn_stats2_k<<<1, 128>>>(pPartE, EDGE_TILES, N_EDGES);
            bn_norm_k<<<edgeHBlocks, TB>>>(pMij, gam_e + l * 128, bet_e + l * 128,
                                           outE, N_EDGES);
        }
    }
}